// round 7
// baseline (speedup 1.0000x reference)
#include <cuda_runtime.h>
#include <cuda_bf16.h>
#include <float.h>
#include <stdint.h>

// Problem constants
#define BB   32
#define DD   256
#define HW   1024
#define NN   (BB*HW)       // 32768
#define KK   1024

#define ZQ_SIZE  (NN*DD)
#define IDX_OFF  ZQ_SIZE
#define LOSS_OFF (ZQ_SIZE + NN)

// GEMM tiling (mma.sync m16n8k8 tf32)
#define MT   128           // rows per CTA
#define NC   64            // codes per chunk
#define NCH  (KK/NC)       // 16 chunks
#define KS   (DD/8)        // 32 k-steps
#define CAP  8
#define WINDOW 4.0e-3f

// ---------------- helpers ----------------
__device__ __forceinline__ float to_tf32(float x) {
    uint32_t u; asm("cvt.rna.tf32.f32 %0, %1;" : "=r"(u) : "f"(x));
    return __uint_as_float(u);
}
__device__ __forceinline__ void mma_tf32(float* d,
                                         float a0, float a1, float a2, float a3,
                                         float b0, float b1) {
    asm volatile(
        "mma.sync.aligned.m16n8k8.row.col.f32.tf32.tf32.f32 "
        "{%0,%1,%2,%3}, {%4,%5,%6,%7}, {%8,%9}, {%0,%1,%2,%3};"
        : "+f"(d[0]), "+f"(d[1]), "+f"(d[2]), "+f"(d[3])
        : "r"(__float_as_uint(a0)), "r"(__float_as_uint(a1)),
          "r"(__float_as_uint(a2)), "r"(__float_as_uint(a3)),
          "r"(__float_as_uint(b0)), "r"(__float_as_uint(b1)));
}

// ---------------- scratch ----------------
__device__ float g_cbnorm[KK];
__device__ float g_znorm[NN];
__device__ float g_zt[(size_t)NN * DD];     // z transposed to [n][d] (exact fp32)
__device__ int   g_idx[NN];
__device__ float g_partial[2048];
__device__ int   g_candk[(size_t)NN * CAP];
__device__ float g_candd[(size_t)NN * CAP];
__device__ float g_bestd[NN];
__device__ int   g_cnum[NN];

// ---------------- kernel 1a: codebook norms (proven exact order) ----------------
__global__ void cbnorm_kernel(const float* __restrict__ cb) {
    int k = blockIdx.x * blockDim.x + threadIdx.x;
    if (k >= KK) return;
    const float* row = cb + k * DD;
    float acc = 0.f;
    for (int d = 0; d < DD; d++) {
        float v = row[d];
        acc = __fadd_rn(acc, __fmul_rn(v, v));
    }
    g_cbnorm[k] = acc;
}

// ---------------- kernel 1b: z norms (proven exact order) ----------------
__global__ void znorm_kernel(const float* __restrict__ z) {
    int n = blockIdx.x * blockDim.x + threadIdx.x;
    if (n >= NN) return;
    int b  = n >> 10;
    int hw = n & 1023;
    const float* p = z + ((size_t)b << 18) + hw;
    float acc = 0.f;
    #pragma unroll 8
    for (int d = 0; d < DD; d++) {
        float v = p[(size_t)d << 10];
        acc = __fadd_rn(acc, __fmul_rn(v, v));
    }
    g_znorm[n] = acc;
}

// ---------------- kernel 1c: transpose z -> g_zt[n][d] ----------------
__global__ void transpose_kernel(const float* __restrict__ z) {
    __shared__ float tile[32][33];
    int b   = blockIdx.z;
    int hw0 = blockIdx.x * 32;
    int d0  = blockIdx.y * 32;
    int tx = threadIdx.x, ty = threadIdx.y;
    #pragma unroll
    for (int j = 0; j < 32; j += 8)
        tile[ty + j][tx] = z[((size_t)(b * DD + d0 + ty + j)) * HW + hw0 + tx];
    __syncthreads();
    #pragma unroll
    for (int j = 0; j < 32; j += 8)
        g_zt[((size_t)(b * HW + hw0 + ty + j)) * DD + d0 + tx] = tile[tx][ty + j];
}

// ---------------- kernel 2: mma.sync TF32 GEMM + approx argmin + candidates ----
// smem: cn[1024] | As[32 ksteps][128 rows][8 frag-interleaved] | Bs[32][64][8]
// Fragment interleave: pos(j<4)=2j holds col k0+j, pos 2j+1 holds col k0+j+4,
// so each lane's (a0,a2)/(a1,a3)/(b0,b1) pair is one float2 LDS.
__global__ void __launch_bounds__(256, 1)
mma_argmin_kernel(const float* __restrict__ cb) {
    extern __shared__ float sm[];
    float* cn = sm;                     // 1024
    float* As = sm + 1024;              // 32768 floats (128 KB)
    float* Bs = sm + 1024 + MT * DD;    // 16384 floats (64 KB)
    float* dist = Bs;                   // reused after MMA consumes Bs

    const int t    = threadIdx.x;
    const int lane = t & 31;
    const int wid  = t >> 5;
    const int wm   = wid & 3;           // 4 warps over M (32 rows each)
    const int wn   = wid >> 2;          // 2 warps over N (32 cols each)
    const int g    = lane >> 2;         // groupID 0..7
    const int tg   = lane & 3;          // thread-in-group
    const int n0   = blockIdx.x * MT;

    for (int i = t; i < KK; i += 256) cn[i] = g_cbnorm[i];

    // stage A: 128 rows x 256 k, tf32, fragment-interleaved
    for (int i4 = t; i4 < MT * DD / 4; i4 += 256) {
        int row = i4 >> 6, k4 = i4 & 63;
        float4 v = *(const float4*)(g_zt + (size_t)(n0 + row) * DD + k4 * 4);
        int ks = k4 >> 1;               // (k4*4)>>3
        int jb = k4 & 1;                // even k4 -> pos 0,2,4,6 ; odd -> 1,3,5,7
        float* dst = As + ((ks * MT + row) << 3) + jb;
        dst[0] = to_tf32(v.x); dst[2] = to_tf32(v.y);
        dst[4] = to_tf32(v.z); dst[6] = to_tf32(v.w);
    }

    const float zn = (t < MT) ? g_znorm[n0 + t] : 0.f;
    float bestd = FLT_MAX;
    int   cnt = 0, ovf = 0;

    for (int c = 0; c < NCH; c++) {
        const int c0 = c * NC;
        __syncthreads();   // prev chunk's dist scan done reading Bs (also A staged, iter 0)

        // stage B: 64 codes x 256 k, tf32, fragment-interleaved
        for (int i4 = t; i4 < NC * DD / 4; i4 += 256) {
            int n = i4 >> 6, k4 = i4 & 63;
            float4 v = *(const float4*)(cb + (size_t)(c0 + n) * DD + k4 * 4);
            int ks = k4 >> 1;
            int jb = k4 & 1;
            float* dst = Bs + ((ks * NC + n) << 3) + jb;
            dst[0] = to_tf32(v.x); dst[2] = to_tf32(v.y);
            dst[4] = to_tf32(v.z); dst[6] = to_tf32(v.w);
        }
        __syncthreads();

        // MMA: warp tile 32x32, 2(m)x4(n) fragments of m16n8k8
        float acc[2][4][4];
        #pragma unroll
        for (int mf = 0; mf < 2; mf++)
            #pragma unroll
            for (int nf = 0; nf < 4; nf++)
                #pragma unroll
                for (int e = 0; e < 4; e++) acc[mf][nf][e] = 0.f;

        #pragma unroll 4
        for (int ks = 0; ks < KS; ks++) {
            const float* ab = As + ((ks * MT + wm * 32) << 3) + tg * 2;
            float2 alo[2], ahi[2];
            #pragma unroll
            for (int mf = 0; mf < 2; mf++) {
                alo[mf] = *(const float2*)(ab + ((mf * 16 + g)     << 3));
                ahi[mf] = *(const float2*)(ab + ((mf * 16 + g + 8) << 3));
            }
            const float* bb = Bs + ((ks * NC + wn * 32) << 3) + tg * 2;
            float2 bf[4];
            #pragma unroll
            for (int nf = 0; nf < 4; nf++)
                bf[nf] = *(const float2*)(bb + ((nf * 8 + g) << 3));
            #pragma unroll
            for (int mf = 0; mf < 2; mf++)
                #pragma unroll
                for (int nf = 0; nf < 4; nf++)
                    mma_tf32(acc[mf][nf],
                             alo[mf].x, ahi[mf].x, alo[mf].y, ahi[mf].y,
                             bf[nf].x, bf[nf].y);
        }
        __syncthreads();   // all warps done reading Bs

        // stage dots into dist[row][col] (row stride 65, conflict-free scan)
        #pragma unroll
        for (int mf = 0; mf < 2; mf++) {
            int row0 = wm * 32 + mf * 16 + g;
            #pragma unroll
            for (int nf = 0; nf < 4; nf++) {
                int col0 = wn * 32 + nf * 8 + 2 * tg;
                dist[row0 * 65 + col0]           = acc[mf][nf][0];
                dist[row0 * 65 + col0 + 1]       = acc[mf][nf][1];
                dist[(row0 + 8) * 65 + col0]     = acc[mf][nf][2];
                dist[(row0 + 8) * 65 + col0 + 1] = acc[mf][nf][3];
            }
        }
        __syncthreads();

        // scan: thread t owns row t, ascending k (first-min semantics preserved)
        if (t < MT) {
            for (int j = 0; j < NC; j++) {
                float s  = dist[t * 65 + j];
                float dt = (zn + cn[c0 + j]) - 2.0f * s;
                int   k  = c0 + j;
                if (dt <= bestd + WINDOW) {
                    if (cnt < CAP) {
                        g_candk[(size_t)(n0 + t) * CAP + cnt] = k;
                        g_candd[(size_t)(n0 + t) * CAP + cnt] = dt;
                        cnt++;
                    } else ovf = 1;
                }
                if (dt < bestd) bestd = dt;
            }
        }
    }

    if (t < MT) {
        g_bestd[n0 + t] = bestd;
        g_cnum[n0 + t]  = ovf ? 255 : cnt;
    }
}

// ---------------- kernel 2b: exact rescore of candidates ----------------
__global__ void rescore_kernel(const float* __restrict__ cb) {
    const int t = threadIdx.x, w = t >> 5, l = t & 31;
    const int n = blockIdx.x * 8 + w;

    int cnum = g_cnum[n];
    if (cnum == 1) {
        if (l == 0) g_idx[n] = g_candk[(size_t)n * CAP];
        return;
    }
    const float zn   = g_znorm[n];
    const float bstd = g_bestd[n];
    const float* zr  = g_zt + (size_t)n * DD;
    float zv[8];
    #pragma unroll
    for (int j = 0; j < 8; j++) zv[j] = zr[l + 32 * j];

    float bd = FLT_MAX;
    int   bk = 0;
    const int m = (cnum == 255) ? KK : cnum;
    for (int c = 0; c < m; c++) {
        int k;
        if (cnum == 255) k = c;
        else {
            k = g_candk[(size_t)n * CAP + c];
            if (g_candd[(size_t)n * CAP + c] > bstd + WINDOW) continue;
        }
        const float* er = cb + (size_t)k * DD;
        float s = 0.f;
        #pragma unroll
        for (int j = 0; j < 8; j++) s = fmaf(zv[j], er[l + 32 * j], s);
        #pragma unroll
        for (int off = 16; off; off >>= 1) s += __shfl_xor_sync(0xFFFFFFFFu, s, off);
        // reference rounding: RN( RN(zn + cn) - 2*dot )
        float dist = __fadd_rn(__fadd_rn(zn, g_cbnorm[k]), -2.0f * s);
        if (dist < bd) { bd = dist; bk = k; }   // ascending k -> first-min tiebreak
    }
    if (l == 0) g_idx[n] = bk;
}

// ---------------- kernel 3: gather + zq_st + indices + loss partials ----------
#define GN 128
#define GD 32
__global__ void gather_kernel(const float* __restrict__ z,
                              const float* __restrict__ cb,
                              float* __restrict__ out,
                              int write_extra) {
    __shared__ int   sidx[GN];
    __shared__ float tile[GD][GN + 1];
    __shared__ float red[8];

    const int t   = threadIdx.x;
    const int n0  = blockIdx.x * GN;
    const int d0  = blockIdx.y * GD;
    const int b   = n0 >> 10;
    const int hw0 = n0 & 1023;

    if (t < GN) sidx[t] = g_idx[n0 + t];
    __syncthreads();

    const int w = t >> 5, l = t & 31;
    for (int nn = w; nn < GN; nn += 8)
        tile[l][nn] = cb[sidx[nn] * DD + d0 + l];
    __syncthreads();

    float lsum = 0.f;
    #pragma unroll
    for (int r = 0; r < (GD * GN) / 256; r++) {
        int i  = r * 256 + t;
        int dd = i >> 7;
        int n  = i & 127;
        int d  = d0 + dd;
        float q  = tile[dd][n];
        int   zi = ((b << 8) + d) * HW + hw0 + n;
        float zv = z[zi];
        float df = __fsub_rn(q, zv);
        out[zi] = __fadd_rn(zv, df);       // zq_st = zp + RN(zq - zp), bitwise
        lsum = fmaf(df, df, lsum);
    }

    #pragma unroll
    for (int off = 16; off; off >>= 1)
        lsum += __shfl_xor_sync(0xFFFFFFFFu, lsum, off);
    if (l == 0) red[w] = lsum;
    __syncthreads();
    if (t == 0) {
        float s = 0.f;
        #pragma unroll
        for (int i = 0; i < 8; i++) s += red[i];
        g_partial[blockIdx.y * gridDim.x + blockIdx.x] = s;
    }
    if (write_extra && blockIdx.y == 0 && t < GN)
        out[IDX_OFF + n0 + t] = (float)sidx[t];
}

// ---------------- kernel 4: finalize loss ----------------
__global__ void loss_kernel(float* __restrict__ out) {
    __shared__ float red[8];
    int t = threadIdx.x;
    float s = 0.f;
    #pragma unroll
    for (int i = 0; i < 8; i++)
        s += g_partial[t * 8 + i];
    #pragma unroll
    for (int off = 16; off; off >>= 1)
        s += __shfl_xor_sync(0xFFFFFFFFu, s, off);
    if ((t & 31) == 0) red[t >> 5] = s;
    __syncthreads();
    if (t == 0) {
        double tot = 0.0;
        #pragma unroll
        for (int i = 0; i < 8; i++) tot += (double)red[i];
        out[LOSS_OFF] = (float)(2.0 * tot / (double)ZQ_SIZE);
    }
}

// ---------------- launch ----------------
extern "C" void kernel_launch(void* const* d_in, const int* in_sizes, int n_in,
                              void* d_out, int out_size) {
    const float* z  = (const float*)d_in[0];
    const float* cb = (const float*)d_in[1];
    float* out = (float*)d_out;

    int write_extra = (out_size >= LOSS_OFF + 1) ? 1 : 0;

    cbnorm_kernel<<<KK / 128, 128>>>(cb);
    znorm_kernel<<<NN / 256, 256>>>(z);
    transpose_kernel<<<dim3(HW / 32, DD / 32, BB), dim3(32, 8)>>>(z);

    size_t smem = (size_t)(1024 + MT * DD + NC * DD) * sizeof(float);  // 200704 B
    cudaFuncSetAttribute(mma_argmin_kernel,
                         cudaFuncAttributeMaxDynamicSharedMemorySize, (int)smem);
    mma_argmin_kernel<<<NN / MT, 256, smem>>>(cb);

    rescore_kernel<<<NN / 8, 256>>>(cb);

    gather_kernel<<<dim3(NN / GN, DD / GD), 256>>>(z, cb, out, write_extra);

    if (write_extra)
        loss_kernel<<<1, 256>>>(out);
}

// round 8
// speedup vs baseline: 2.6891x; 2.6891x over previous
#include <cuda_runtime.h>
#include <cuda_bf16.h>
#include <float.h>
#include <stdint.h>

// Problem constants
#define BB   32
#define DD   256
#define HW   1024
#define NN   (BB*HW)       // 32768
#define KK   1024

#define ZQ_SIZE  (NN*DD)
#define IDX_OFF  ZQ_SIZE
#define LOSS_OFF (ZQ_SIZE + NN)

// GEMM tiling (mma.sync m16n8k8 tf32)
#define MT    128          // rows per CTA
#define NC    128          // codes per chunk
#define NCH   (KK/NC)      // 8 chunks
#define DCH   128          // d per B stage
#define KSS   (DCH/8)      // 16 k-steps per stage
#define CAP   16
#define WINDOW 4.0e-3f

// ---------------- helpers ----------------
__device__ __forceinline__ float to_tf32(float x) {
    uint32_t u; asm("cvt.rna.tf32.f32 %0, %1;" : "=r"(u) : "f"(x));
    return __uint_as_float(u);
}
__device__ __forceinline__ void mma_tf32(float* d,
                                         float a0, float a1, float a2, float a3,
                                         float b0, float b1) {
    asm volatile(
        "mma.sync.aligned.m16n8k8.row.col.f32.tf32.tf32.f32 "
        "{%0,%1,%2,%3}, {%4,%5,%6,%7}, {%8,%9}, {%0,%1,%2,%3};"
        : "+f"(d[0]), "+f"(d[1]), "+f"(d[2]), "+f"(d[3])
        : "r"(__float_as_uint(a0)), "r"(__float_as_uint(a1)),
          "r"(__float_as_uint(a2)), "r"(__float_as_uint(a3)),
          "r"(__float_as_uint(b0)), "r"(__float_as_uint(b1)));
}

// ---------------- scratch ----------------
__device__ float g_cbnorm[KK];
__device__ float g_znorm[NN];
__device__ float g_zt[(size_t)NN * DD];     // z transposed to [n][d]
__device__ int   g_idx[NN];
__device__ float g_partial[2048];
__device__ int   g_candk[(size_t)NN * CAP];
__device__ float g_candd[(size_t)NN * CAP];
__device__ float g_bestd[NN];
__device__ int   g_cnum[NN];

// ---------------- kernel 1a: codebook norms (proven exact order) ----------------
__global__ void cbnorm_kernel(const float* __restrict__ cb) {
    int k = blockIdx.x * blockDim.x + threadIdx.x;
    if (k >= KK) return;
    const float* row = cb + k * DD;
    float acc = 0.f;
    for (int d = 0; d < DD; d++) {
        float v = row[d];
        acc = __fadd_rn(acc, __fmul_rn(v, v));
    }
    g_cbnorm[k] = acc;
}

// ---------------- kernel 1b: z norms (proven exact order) ----------------
__global__ void znorm_kernel(const float* __restrict__ z) {
    int n = blockIdx.x * blockDim.x + threadIdx.x;
    if (n >= NN) return;
    int b  = n >> 10;
    int hw = n & 1023;
    const float* p = z + ((size_t)b << 18) + hw;
    float acc = 0.f;
    #pragma unroll 8
    for (int d = 0; d < DD; d++) {
        float v = p[(size_t)d << 10];
        acc = __fadd_rn(acc, __fmul_rn(v, v));
    }
    g_znorm[n] = acc;
}

// ---------------- kernel 1c: transpose z -> g_zt[n][d] ----------------
__global__ void transpose_kernel(const float* __restrict__ z) {
    __shared__ float tile[32][33];
    int b   = blockIdx.z;
    int hw0 = blockIdx.x * 32;
    int d0  = blockIdx.y * 32;
    int tx = threadIdx.x, ty = threadIdx.y;
    #pragma unroll
    for (int j = 0; j < 32; j += 8)
        tile[ty + j][tx] = z[((size_t)(b * DD + d0 + ty + j)) * HW + hw0 + tx];
    __syncthreads();
    #pragma unroll
    for (int j = 0; j < 32; j += 8)
        g_zt[((size_t)(b * HW + hw0 + ty + j)) * DD + d0 + tx] = tile[tx][ty + j];
}

// ---------------- kernel 2: mma.sync TF32 GEMM + approx argmin + candidates ----
// 512 threads / 16 warps (4M x 4N warp grid, 32x32 warp tiles over 128x128).
// smem: cn[1024] | As[32 ksteps][128 rows][8 interleaved] | Bs[16][128][8]
// Fragment interleave (hardware-validated in R7): pos 2j <-> col k0+j,
// pos 2j+1 <-> col k0+j+4, so each lane's fragment pair is one float2 LDS.
__global__ void __launch_bounds__(512, 1)
mma_argmin_kernel(const float* __restrict__ cb) {
    extern __shared__ float sm[];
    float* cn = sm;                       // 1024
    float* As = sm + 1024;                // 32768 floats (128 KB)
    float* Bs = sm + 1024 + MT * DD;      // 16384 floats (64 KB)
    float* dist = Bs;                     // transposed [col][row], reused

    const int t    = threadIdx.x;
    const int lane = t & 31;
    const int wid  = t >> 5;
    const int wm   = wid & 3;             // 4 warps over M (32 rows each)
    const int wn   = wid >> 2;            // 4 warps over N (32 cols each)
    const int g    = lane >> 2;           // groupID 0..7
    const int tg   = lane & 3;            // thread-in-group
    const int n0   = blockIdx.x * MT;

    for (int i = t; i < KK; i += 512) cn[i] = g_cbnorm[i];

    // stage A: 128 rows x 256 k, tf32, fragment-interleaved
    for (int i4 = t; i4 < MT * DD / 4; i4 += 512) {
        int row = i4 >> 6, k4 = i4 & 63;
        float4 v = *(const float4*)(g_zt + (size_t)(n0 + row) * DD + k4 * 4);
        int ks = k4 >> 1;
        int jb = k4 & 1;
        float* dst = As + ((ks * MT + row) << 3) + jb;
        dst[0] = to_tf32(v.x); dst[2] = to_tf32(v.y);
        dst[4] = to_tf32(v.z); dst[6] = to_tf32(v.w);
    }

    const float zn = (t < MT) ? g_znorm[n0 + t] : 0.f;
    float bestd = FLT_MAX;
    int   cnt = 0, ovf = 0;
    float cd[CAP];
    int   ck[CAP];

    for (int c = 0; c < NCH; c++) {
        const int c0 = c * NC;

        float acc[2][4][4];
        #pragma unroll
        for (int mf = 0; mf < 2; mf++)
            #pragma unroll
            for (int nf = 0; nf < 4; nf++)
                #pragma unroll
                for (int e = 0; e < 4; e++) acc[mf][nf][e] = 0.f;

        #pragma unroll
        for (int dch = 0; dch < DD / DCH; dch++) {
            __syncthreads();   // prev scan / prev stage reads done with Bs
            // stage B: 128 codes x 128 d, tf32, fragment-interleaved
            const int d0 = dch * DCH;
            for (int i4 = t; i4 < NC * DCH / 4; i4 += 512) {
                int n = i4 >> 5, k4 = i4 & 31;
                float4 v = *(const float4*)(cb + (size_t)(c0 + n) * DD + d0 + k4 * 4);
                int ks = k4 >> 1;
                int jb = k4 & 1;
                float* dst = Bs + ((ks * NC + n) << 3) + jb;
                dst[0] = to_tf32(v.x); dst[2] = to_tf32(v.y);
                dst[4] = to_tf32(v.z); dst[6] = to_tf32(v.w);
            }
            __syncthreads();

            #pragma unroll 4
            for (int ks = 0; ks < KSS; ks++) {
                const int ksA = dch * KSS + ks;
                const float* ab = As + ((ksA * MT + wm * 32) << 3) + tg * 2;
                float2 alo[2], ahi[2];
                #pragma unroll
                for (int mf = 0; mf < 2; mf++) {
                    alo[mf] = *(const float2*)(ab + ((mf * 16 + g)     << 3));
                    ahi[mf] = *(const float2*)(ab + ((mf * 16 + g + 8) << 3));
                }
                const float* bb = Bs + ((ks * NC + wn * 32) << 3) + tg * 2;
                float2 bf[4];
                #pragma unroll
                for (int nf = 0; nf < 4; nf++)
                    bf[nf] = *(const float2*)(bb + ((nf * 8 + g) << 3));
                #pragma unroll
                for (int mf = 0; mf < 2; mf++)
                    #pragma unroll
                    for (int nf = 0; nf < 4; nf++)
                        mma_tf32(acc[mf][nf],
                                 alo[mf].x, ahi[mf].x, alo[mf].y, ahi[mf].y,
                                 bf[nf].x, bf[nf].y);
            }
        }
        __syncthreads();   // all warps done reading Bs before dist overwrite

        // dist transposed: dist[col*128 + row] -> stride-1 scan across threads
        #pragma unroll
        for (int mf = 0; mf < 2; mf++) {
            int row0 = wm * 32 + mf * 16 + g;
            #pragma unroll
            for (int nf = 0; nf < 4; nf++) {
                int col0 = wn * 32 + nf * 8 + 2 * tg;
                dist[col0 * MT + row0]             = acc[mf][nf][0];
                dist[(col0 + 1) * MT + row0]       = acc[mf][nf][1];
                dist[col0 * MT + row0 + 8]         = acc[mf][nf][2];
                dist[(col0 + 1) * MT + row0 + 8]   = acc[mf][nf][3];
            }
        }
        __syncthreads();

        // scan: thread t owns row t, ascending k; prune-on-full candidate list
        if (t < MT) {
            for (int j = 0; j < NC; j++) {
                float s  = dist[j * MT + t];
                float dt = (zn + cn[c0 + j]) - 2.0f * s;
                if (dt <= bestd + WINDOW) {
                    if (cnt == CAP) {          // prune against tightened bestd
                        int m2 = 0;
                        #pragma unroll
                        for (int q = 0; q < CAP; q++)
                            if (cd[q] <= bestd + WINDOW) { cd[m2] = cd[q]; ck[m2] = ck[q]; m2++; }
                        cnt = m2;
                    }
                    if (cnt < CAP) { ck[cnt] = c0 + j; cd[cnt] = dt; cnt++; }
                    else ovf = 1;
                }
                if (dt < bestd) bestd = dt;
            }
        }
    }

    if (t < MT) {
        g_bestd[n0 + t] = bestd;
        g_cnum[n0 + t]  = ovf ? 255 : cnt;
        for (int q = 0; q < cnt; q++) {
            g_candk[(size_t)(n0 + t) * CAP + q] = ck[q];
            g_candd[(size_t)(n0 + t) * CAP + q] = cd[q];
        }
    }
}

// ---------------- kernel 2b: exact rescore of candidates ----------------
__global__ void rescore_kernel(const float* __restrict__ cb) {
    const int t = threadIdx.x, w = t >> 5, l = t & 31;
    const int n = blockIdx.x * 8 + w;

    int cnum = g_cnum[n];
    const float bstd = g_bestd[n];

    if (cnum != 255) {
        // count survivors within final window; single survivor -> done
        int m2 = 0, lastk = 0;
        for (int c = 0; c < cnum; c++)
            if (g_candd[(size_t)n * CAP + c] <= bstd + WINDOW) {
                m2++; lastk = g_candk[(size_t)n * CAP + c];
            }
        if (m2 == 1) {
            if (l == 0) g_idx[n] = lastk;
            return;
        }
    }

    const float zn  = g_znorm[n];
    const float* zr = g_zt + (size_t)n * DD;
    float zv[8];
    #pragma unroll
    for (int j = 0; j < 8; j++) zv[j] = zr[l + 32 * j];

    float bd = FLT_MAX;
    int   bk = 0;
    const int m = (cnum == 255) ? KK : cnum;
    for (int c = 0; c < m; c++) {
        int k;
        if (cnum == 255) k = c;
        else {
            k = g_candk[(size_t)n * CAP + c];
            if (g_candd[(size_t)n * CAP + c] > bstd + WINDOW) continue;
        }
        const float* er = cb + (size_t)k * DD;
        float s = 0.f;
        #pragma unroll
        for (int j = 0; j < 8; j++) s = fmaf(zv[j], er[l + 32 * j], s);
        #pragma unroll
        for (int off = 16; off; off >>= 1) s += __shfl_xor_sync(0xFFFFFFFFu, s, off);
        // reference rounding: RN( RN(zn + cn) - 2*dot )
        float dist = __fadd_rn(__fadd_rn(zn, g_cbnorm[k]), -2.0f * s);
        if (dist < bd) { bd = dist; bk = k; }   // ascending k -> first-min tiebreak
    }
    if (l == 0) g_idx[n] = bk;
}

// ---------------- kernel 3: gather + zq_st + indices + loss partials ----------
#define GN 128
#define GD 32
__global__ void gather_kernel(const float* __restrict__ z,
                              const float* __restrict__ cb,
                              float* __restrict__ out,
                              int write_extra) {
    __shared__ int   sidx[GN];
    __shared__ float tile[GD][GN + 1];
    __shared__ float red[8];

    const int t   = threadIdx.x;
    const int n0  = blockIdx.x * GN;
    const int d0  = blockIdx.y * GD;
    const int b   = n0 >> 10;
    const int hw0 = n0 & 1023;

    if (t < GN) sidx[t] = g_idx[n0 + t];
    __syncthreads();

    const int w = t >> 5, l = t & 31;
    for (int nn = w; nn < GN; nn += 8)
        tile[l][nn] = cb[sidx[nn] * DD + d0 + l];
    __syncthreads();

    float lsum = 0.f;
    #pragma unroll
    for (int r = 0; r < (GD * GN) / 256; r++) {
        int i  = r * 256 + t;
        int dd = i >> 7;
        int n  = i & 127;
        int d  = d0 + dd;
        float q  = tile[dd][n];
        int   zi = ((b << 8) + d) * HW + hw0 + n;
        float zv = z[zi];
        float df = __fsub_rn(q, zv);
        out[zi] = __fadd_rn(zv, df);       // zq_st = zp + RN(zq - zp), bitwise
        lsum = fmaf(df, df, lsum);
    }

    #pragma unroll
    for (int off = 16; off; off >>= 1)
        lsum += __shfl_xor_sync(0xFFFFFFFFu, lsum, off);
    if (l == 0) red[w] = lsum;
    __syncthreads();
    if (t == 0) {
        float s = 0.f;
        #pragma unroll
        for (int i = 0; i < 8; i++) s += red[i];
        g_partial[blockIdx.y * gridDim.x + blockIdx.x] = s;
    }
    if (write_extra && blockIdx.y == 0 && t < GN)
        out[IDX_OFF + n0 + t] = (float)sidx[t];
}

// ---------------- kernel 4: finalize loss ----------------
__global__ void loss_kernel(float* __restrict__ out) {
    __shared__ float red[8];
    int t = threadIdx.x;
    float s = 0.f;
    #pragma unroll
    for (int i = 0; i < 8; i++)
        s += g_partial[t * 8 + i];
    #pragma unroll
    for (int off = 16; off; off >>= 1)
        s += __shfl_xor_sync(0xFFFFFFFFu, s, off);
    if ((t & 31) == 0) red[t >> 5] = s;
    __syncthreads();
    if (t == 0) {
        double tot = 0.0;
        #pragma unroll
        for (int i = 0; i < 8; i++) tot += (double)red[i];
        out[LOSS_OFF] = (float)(2.0 * tot / (double)ZQ_SIZE);
    }
}

// ---------------- launch ----------------
extern "C" void kernel_launch(void* const* d_in, const int* in_sizes, int n_in,
                              void* d_out, int out_size) {
    const float* z  = (const float*)d_in[0];
    const float* cb = (const float*)d_in[1];
    float* out = (float*)d_out;

    int write_extra = (out_size >= LOSS_OFF + 1) ? 1 : 0;

    cbnorm_kernel<<<KK / 128, 128>>>(cb);
    znorm_kernel<<<NN / 256, 256>>>(z);
    transpose_kernel<<<dim3(HW / 32, DD / 32, BB), dim3(32, 8)>>>(z);

    size_t smem = (size_t)(1024 + MT * DD + KSS * NC * 8) * sizeof(float);  // 200704 B
    cudaFuncSetAttribute(mma_argmin_kernel,
                         cudaFuncAttributeMaxDynamicSharedMemorySize, (int)smem);
    mma_argmin_kernel<<<NN / MT, 512, smem>>>(cb);

    rescore_kernel<<<NN / 8, 256>>>(cb);

    gather_kernel<<<dim3(NN / GN, DD / GD), 256>>>(z, cb, out, write_extra);

    if (write_extra)
        loss_kernel<<<1, 256>>>(out);
}

// round 9
// speedup vs baseline: 3.7196x; 1.3832x over previous
#include <cuda_runtime.h>
#include <cuda_bf16.h>
#include <float.h>
#include <stdint.h>

// Problem constants
#define BB   32
#define DD   256
#define HW   1024
#define NN   (BB*HW)       // 32768
#define KK   1024

#define ZQ_SIZE  (NN*DD)
#define IDX_OFF  ZQ_SIZE
#define LOSS_OFF (ZQ_SIZE + NN)

// GEMM tiling (mma.sync m16n8k8 tf32) — R7-validated fragment layout
#define MT   128           // rows per CTA
#define NC   64            // codes per chunk
#define NCH  (KK/NC)       // 16 chunks
#define KS   (DD/8)        // 32 k-steps
#define WINDOW 4.0e-3f

// ---------------- helpers ----------------
__device__ __forceinline__ float to_tf32(float x) {
    uint32_t u; asm("cvt.rna.tf32.f32 %0, %1;" : "=r"(u) : "f"(x));
    return __uint_as_float(u);
}
__device__ __forceinline__ void mma_tf32(float* d,
                                         float a0, float a1, float a2, float a3,
                                         float b0, float b1) {
    asm volatile(
        "mma.sync.aligned.m16n8k8.row.col.f32.tf32.tf32.f32 "
        "{%0,%1,%2,%3}, {%4,%5,%6,%7}, {%8,%9}, {%0,%1,%2,%3};"
        : "+f"(d[0]), "+f"(d[1]), "+f"(d[2]), "+f"(d[3])
        : "r"(__float_as_uint(a0)), "r"(__float_as_uint(a1)),
          "r"(__float_as_uint(a2)), "r"(__float_as_uint(a3)),
          "r"(__float_as_uint(b0)), "r"(__float_as_uint(b1)));
}

// ---------------- scratch ----------------
__device__ float g_cbnorm[KK];
__device__ float g_znorm[NN];
__device__ float g_zt[(size_t)NN * DD];     // z transposed to [n][d]
__device__ float g_dots[(size_t)NN * KK];   // 128MB: raw z.e dot products
__device__ int   g_idx[NN];
__device__ float g_partial[2048];

// ---------------- kernel 1a: codebook norms (proven exact order) ----------------
__global__ void cbnorm_kernel(const float* __restrict__ cb) {
    int k = blockIdx.x * blockDim.x + threadIdx.x;
    if (k >= KK) return;
    const float* row = cb + k * DD;
    float acc = 0.f;
    for (int d = 0; d < DD; d++) {
        float v = row[d];
        acc = __fadd_rn(acc, __fmul_rn(v, v));
    }
    g_cbnorm[k] = acc;
}

// ---------------- kernel 1b: z norms (proven exact order) ----------------
__global__ void znorm_kernel(const float* __restrict__ z) {
    int n = blockIdx.x * blockDim.x + threadIdx.x;
    if (n >= NN) return;
    int b  = n >> 10;
    int hw = n & 1023;
    const float* p = z + ((size_t)b << 18) + hw;
    float acc = 0.f;
    #pragma unroll 8
    for (int d = 0; d < DD; d++) {
        float v = p[(size_t)d << 10];
        acc = __fadd_rn(acc, __fmul_rn(v, v));
    }
    g_znorm[n] = acc;
}

// ---------------- kernel 1c: transpose z -> g_zt[n][d] ----------------
__global__ void transpose_kernel(const float* __restrict__ z) {
    __shared__ float tile[32][33];
    int b   = blockIdx.z;
    int hw0 = blockIdx.x * 32;
    int d0  = blockIdx.y * 32;
    int tx = threadIdx.x, ty = threadIdx.y;
    #pragma unroll
    for (int j = 0; j < 32; j += 8)
        tile[ty + j][tx] = z[((size_t)(b * DD + d0 + ty + j)) * HW + hw0 + tx];
    __syncthreads();
    #pragma unroll
    for (int j = 0; j < 32; j += 8)
        g_zt[((size_t)(b * HW + hw0 + ty + j)) * DD + d0 + tx] = tile[tx][ty + j];
}

// ---------------- kernel 2: PURE mma.sync TF32 GEMM -> g_dots ----------------
// 256 threads / 8 warps: 4 M-warps x 2 N-warps, 32x32 warp tiles.
// smem: As[32 ksteps][128 rows][8 interleaved] | Bs[32][64][8]  (192 KB)
// Fragment interleave (validated R7): pos 2j <-> col k0+j, pos 2j+1 <-> k0+j+4.
__global__ void __launch_bounds__(256, 1)
mma_dots_kernel(const float* __restrict__ cb) {
    extern __shared__ float sm[];
    float* As = sm;                     // 32768 floats (128 KB)
    float* Bs = sm + MT * DD;           // 16384 floats (64 KB)

    const int t    = threadIdx.x;
    const int lane = t & 31;
    const int wid  = t >> 5;
    const int wm   = wid & 3;           // 4 warps over M (32 rows each)
    const int wn   = wid >> 2;          // 2 warps over N (32 cols each)
    const int g    = lane >> 2;         // groupID 0..7
    const int tg   = lane & 3;          // thread-in-group
    const int n0   = blockIdx.x * MT;

    // stage A: 128 rows x 256 k, tf32, fragment-interleaved
    for (int i4 = t; i4 < MT * DD / 4; i4 += 256) {
        int row = i4 >> 6, k4 = i4 & 63;
        float4 v = *(const float4*)(g_zt + (size_t)(n0 + row) * DD + k4 * 4);
        int ks = k4 >> 1;
        int jb = k4 & 1;
        float* dst = As + ((ks * MT + row) << 3) + jb;
        dst[0] = to_tf32(v.x); dst[2] = to_tf32(v.y);
        dst[4] = to_tf32(v.z); dst[6] = to_tf32(v.w);
    }

    for (int c = 0; c < NCH; c++) {
        const int c0 = c * NC;
        __syncthreads();   // all warps done reading Bs (and A staged, iter 0)

        // stage B: 64 codes x 256 k, tf32, fragment-interleaved
        for (int i4 = t; i4 < NC * DD / 4; i4 += 256) {
            int n = i4 >> 6, k4 = i4 & 63;
            float4 v = *(const float4*)(cb + (size_t)(c0 + n) * DD + k4 * 4);
            int ks = k4 >> 1;
            int jb = k4 & 1;
            float* dst = Bs + ((ks * NC + n) << 3) + jb;
            dst[0] = to_tf32(v.x); dst[2] = to_tf32(v.y);
            dst[4] = to_tf32(v.z); dst[6] = to_tf32(v.w);
        }
        __syncthreads();

        float acc[2][4][4];
        #pragma unroll
        for (int mf = 0; mf < 2; mf++)
            #pragma unroll
            for (int nf = 0; nf < 4; nf++)
                #pragma unroll
                for (int e = 0; e < 4; e++) acc[mf][nf][e] = 0.f;

        #pragma unroll 4
        for (int ks = 0; ks < KS; ks++) {
            const float* ab = As + ((ks * MT + wm * 32) << 3) + tg * 2;
            float2 alo[2], ahi[2];
            #pragma unroll
            for (int mf = 0; mf < 2; mf++) {
                alo[mf] = *(const float2*)(ab + ((mf * 16 + g)     << 3));
                ahi[mf] = *(const float2*)(ab + ((mf * 16 + g + 8) << 3));
            }
            const float* bb = Bs + ((ks * NC + wn * 32) << 3) + tg * 2;
            float2 bf[4];
            #pragma unroll
            for (int nf = 0; nf < 4; nf++)
                bf[nf] = *(const float2*)(bb + ((nf * 8 + g) << 3));
            #pragma unroll
            for (int mf = 0; mf < 2; mf++)
                #pragma unroll
                for (int nf = 0; nf < 4; nf++)
                    mma_tf32(acc[mf][nf],
                             alo[mf].x, ahi[mf].x, alo[mf].y, ahi[mf].y,
                             bf[nf].x, bf[nf].y);
        }

        // write dots straight to global: lane quads cover full 32B sectors
        #pragma unroll
        for (int mf = 0; mf < 2; mf++) {
            int row0 = wm * 32 + mf * 16 + g;
            #pragma unroll
            for (int nf = 0; nf < 4; nf++) {
                int col0 = c0 + wn * 32 + nf * 8 + 2 * tg;
                *(float2*)(g_dots + ((size_t)(n0 + row0) << 10) + col0)
                    = make_float2(acc[mf][nf][0], acc[mf][nf][1]);
                *(float2*)(g_dots + ((size_t)(n0 + row0 + 8) << 10) + col0)
                    = make_float2(acc[mf][nf][2], acc[mf][nf][3]);
            }
        }
    }
}

// ---------------- kernel 2b: scan dots -> min -> candidates -> exact rescore ----
// Warp per row. Approx dt only gates candidates; exactness comes from the
// proven reference-rounded rescore with (dist, k) lowest-index tiebreak.
#define SCW 8
__global__ void scan_rescore_kernel(const float* __restrict__ cb) {
    __shared__ int s_cnt[SCW];
    __shared__ int s_k[SCW][8];

    const int t = threadIdx.x, w = t >> 5, l = t & 31;
    const int n = blockIdx.x * SCW + w;

    const float zn = g_znorm[n];
    const float* dr = g_dots + ((size_t)n << 10);

    float dt[32];
    float mn = FLT_MAX;
    #pragma unroll
    for (int i = 0; i < 8; i++) {
        float4 s4 = *(const float4*)(dr + i * 128 + l * 4);
        float4 c4 = *(const float4*)(g_cbnorm + i * 128 + l * 4);
        dt[i * 4 + 0] = (zn + c4.x) - 2.0f * s4.x;
        dt[i * 4 + 1] = (zn + c4.y) - 2.0f * s4.y;
        dt[i * 4 + 2] = (zn + c4.z) - 2.0f * s4.z;
        dt[i * 4 + 3] = (zn + c4.w) - 2.0f * s4.w;
        mn = fminf(mn, fminf(fminf(dt[i*4], dt[i*4+1]), fminf(dt[i*4+2], dt[i*4+3])));
    }
    #pragma unroll
    for (int off = 16; off; off >>= 1)
        mn = fminf(mn, __shfl_xor_sync(0xFFFFFFFFu, mn, off));

    if (l == 0) s_cnt[w] = 0;
    __syncwarp();

    const float thr = mn + WINDOW;
    #pragma unroll
    for (int i = 0; i < 8; i++)
        #pragma unroll
        for (int q = 0; q < 4; q++)
            if (dt[i * 4 + q] <= thr) {
                int pos = atomicAdd(&s_cnt[w], 1);
                if (pos < 8) s_k[w][pos] = i * 128 + l * 4 + q;
            }
    __syncwarp();
    const int m = s_cnt[w];

    if (m == 1) {                       // sound: true argmin is always admitted
        if (l == 0) g_idx[n] = s_k[w][0];
        return;
    }

    const float* zr = g_zt + (size_t)n * DD;
    float zv[8];
    #pragma unroll
    for (int j = 0; j < 8; j++) zv[j] = zr[l + 32 * j];

    float bd = FLT_MAX;
    int   bk = 0x7FFFFFFF;
    const int cmax = (m <= 8) ? m : KK; // overflow (never expected) -> full scan
    for (int c = 0; c < cmax; c++) {
        int k = (m <= 8) ? s_k[w][c] : c;
        const float* er = cb + (size_t)k * DD;
        float s = 0.f;
        #pragma unroll
        for (int j = 0; j < 8; j++) s = fmaf(zv[j], er[l + 32 * j], s);
        #pragma unroll
        for (int off = 16; off; off >>= 1) s += __shfl_xor_sync(0xFFFFFFFFu, s, off);
        // reference rounding: RN( RN(zn + cn) - 2*dot )
        float dist = __fadd_rn(__fadd_rn(zn, g_cbnorm[k]), -2.0f * s);
        if (dist < bd || (dist == bd && k < bk)) { bd = dist; bk = k; }
    }
    if (l == 0) g_idx[n] = bk;
}

// ---------------- kernel 3: gather + zq_st + indices + loss partials ----------
#define GN 128
#define GD 32
__global__ void gather_kernel(const float* __restrict__ z,
                              const float* __restrict__ cb,
                              float* __restrict__ out,
                              int write_extra) {
    __shared__ int   sidx[GN];
    __shared__ float tile[GD][GN + 1];
    __shared__ float red[8];

    const int t   = threadIdx.x;
    const int n0  = blockIdx.x * GN;
    const int d0  = blockIdx.y * GD;
    const int b   = n0 >> 10;
    const int hw0 = n0 & 1023;

    if (t < GN) sidx[t] = g_idx[n0 + t];
    __syncthreads();

    const int w = t >> 5, l = t & 31;
    for (int nn = w; nn < GN; nn += 8)
        tile[l][nn] = cb[sidx[nn] * DD + d0 + l];
    __syncthreads();

    float lsum = 0.f;
    #pragma unroll
    for (int r = 0; r < (GD * GN) / 256; r++) {
        int i  = r * 256 + t;
        int dd = i >> 7;
        int n  = i & 127;
        int d  = d0 + dd;
        float q  = tile[dd][n];
        int   zi = ((b << 8) + d) * HW + hw0 + n;
        float zv = z[zi];
        float df = __fsub_rn(q, zv);
        out[zi] = __fadd_rn(zv, df);       // zq_st = zp + RN(zq - zp), bitwise
        lsum = fmaf(df, df, lsum);
    }

    #pragma unroll
    for (int off = 16; off; off >>= 1)
        lsum += __shfl_xor_sync(0xFFFFFFFFu, lsum, off);
    if (l == 0) red[w] = lsum;
    __syncthreads();
    if (t == 0) {
        float s = 0.f;
        #pragma unroll
        for (int i = 0; i < 8; i++) s += red[i];
        g_partial[blockIdx.y * gridDim.x + blockIdx.x] = s;
    }
    if (write_extra && blockIdx.y == 0 && t < GN)
        out[IDX_OFF + n0 + t] = (float)sidx[t];
}

// ---------------- kernel 4: finalize loss ----------------
__global__ void loss_kernel(float* __restrict__ out) {
    __shared__ float red[8];
    int t = threadIdx.x;
    float s = 0.f;
    #pragma unroll
    for (int i = 0; i < 8; i++)
        s += g_partial[t * 8 + i];
    #pragma unroll
    for (int off = 16; off; off >>= 1)
        s += __shfl_xor_sync(0xFFFFFFFFu, s, off);
    if ((t & 31) == 0) red[t >> 5] = s;
    __syncthreads();
    if (t == 0) {
        double tot = 0.0;
        #pragma unroll
        for (int i = 0; i < 8; i++) tot += (double)red[i];
        out[LOSS_OFF] = (float)(2.0 * tot / (double)ZQ_SIZE);
    }
}

// ---------------- launch ----------------
extern "C" void kernel_launch(void* const* d_in, const int* in_sizes, int n_in,
                              void* d_out, int out_size) {
    const float* z  = (const float*)d_in[0];
    const float* cb = (const float*)d_in[1];
    float* out = (float*)d_out;

    int write_extra = (out_size >= LOSS_OFF + 1) ? 1 : 0;

    cbnorm_kernel<<<KK / 128, 128>>>(cb);
    znorm_kernel<<<NN / 256, 256>>>(z);
    transpose_kernel<<<dim3(HW / 32, DD / 32, BB), dim3(32, 8)>>>(z);

    size_t smem = (size_t)(MT * DD + NC * DD) * sizeof(float);   // 196608 B
    cudaFuncSetAttribute(mma_dots_kernel,
                         cudaFuncAttributeMaxDynamicSharedMemorySize, (int)smem);
    mma_dots_kernel<<<NN / MT, 256, smem>>>(cb);

    scan_rescore_kernel<<<NN / SCW, 256>>>(cb);

    gather_kernel<<<dim3(NN / GN, DD / GD), 256>>>(z, cb, out, write_extra);

    if (write_extra)
        loss_kernel<<<1, 256>>>(out);
}